// round 1
// baseline (speedup 1.0000x reference)
#include <cuda_runtime.h>
#include <math.h>

#define NROWS 16384
#define DDIM  256
#define INV_TEMP (1.0f / 0.07f)

#define BM 128
#define BN 128
#define BK 32
#define NSPLIT 4
#define CPB (NROWS / NSPLIT)   // columns per block: 4096

// Scratch (device globals: no allocation allowed in kernel_launch)
__device__ float g_qn[NROWS * DDIM];
__device__ float g_kn[NROWS * DDIM];
__device__ float g_S[NROWS];      // sum_j exp(l_ij - M)
__device__ float g_diag[NROWS];   // l_ii

// ---------------------------------------------------------------------------
// Kernel 1: L2 normalize (one warp per row). Also zeroes g_S each launch so
// the graph replays are self-contained.
// ---------------------------------------------------------------------------
__global__ void normalize_kernel(const float* __restrict__ q,
                                 const float* __restrict__ k) {
    int warp = threadIdx.x >> 5;
    int lane = threadIdx.x & 31;
    int row  = blockIdx.x * (blockDim.x >> 5) + warp;
    if (row >= NROWS) return;

    const float* src = (blockIdx.y == 0) ? q : k;
    float*       dst = (blockIdx.y == 0) ? g_qn : g_kn;

    const float4* s4 = reinterpret_cast<const float4*>(src + (size_t)row * DDIM);
    float4 v0 = s4[lane];
    float4 v1 = s4[lane + 32];

    float ss = v0.x * v0.x + v0.y * v0.y + v0.z * v0.z + v0.w * v0.w
             + v1.x * v1.x + v1.y * v1.y + v1.z * v1.z + v1.w * v1.w;
#pragma unroll
    for (int o = 16; o; o >>= 1) ss += __shfl_xor_sync(0xffffffffu, ss, o);

    float inv = 1.0f / fmaxf(sqrtf(ss), 1e-12f);

    v0.x *= inv; v0.y *= inv; v0.z *= inv; v0.w *= inv;
    v1.x *= inv; v1.y *= inv; v1.z *= inv; v1.w *= inv;

    float4* d4 = reinterpret_cast<float4*>(dst + (size_t)row * DDIM);
    d4[lane]      = v0;
    d4[lane + 32] = v1;

    if (blockIdx.y == 0 && lane == 0) g_S[row] = 0.0f;
}

// ---------------------------------------------------------------------------
// Kernel 2: fused GEMM (qn @ kn^T) + exp-sum accumulation + diag capture.
// Block = 128-row band x 4096-col span; inner loop over 128-col tiles.
// Fixed LSE shift M = 1/TEMP (logits are bounded by it since rows are unit).
// ---------------------------------------------------------------------------
__global__ void __launch_bounds__(256, 2) gemm_lse_kernel() {
    __shared__ float As[BK][BM];   // A tile transposed: As[k][row]
    __shared__ float Bs[BK][BN];   // B tile transposed: Bs[k][col]

    const int tid = threadIdx.x;
    const int ty  = tid >> 4;          // 0..15 -> row group
    const int tx  = tid & 15;          // 0..15 -> col group
    const int rowBase  = blockIdx.x * BM;
    const int colStart = blockIdx.y * CPB;

    float rowsum[8];
#pragma unroll
    for (int r = 0; r < 8; r++) rowsum[r] = 0.0f;

    for (int ct = 0; ct < CPB / BN; ct++) {
        const int colBase = colStart + ct * BN;

        float acc[8][8];
#pragma unroll
        for (int r = 0; r < 8; r++)
#pragma unroll
            for (int c = 0; c < 8; c++) acc[r][c] = 0.0f;

        for (int kk = 0; kk < DDIM; kk += BK) {
            // Cooperative load of 128x32 tiles (transposed into SMEM).
#pragma unroll
            for (int l = 0; l < 4; l++) {
                int idx = tid + l * 256;        // 0..1023 float4 slots
                int r   = idx >> 3;             // 8 float4 per row of 32
                int kq  = (idx & 7) << 2;
                float4 va = *reinterpret_cast<const float4*>(
                    &g_qn[(size_t)(rowBase + r) * DDIM + kk + kq]);
                As[kq + 0][r] = va.x; As[kq + 1][r] = va.y;
                As[kq + 2][r] = va.z; As[kq + 3][r] = va.w;
                float4 vb = *reinterpret_cast<const float4*>(
                    &g_kn[(size_t)(colBase + r) * DDIM + kk + kq]);
                Bs[kq + 0][r] = vb.x; Bs[kq + 1][r] = vb.y;
                Bs[kq + 2][r] = vb.z; Bs[kq + 3][r] = vb.w;
            }
            __syncthreads();

#pragma unroll
            for (int k = 0; k < BK; k++) {
                float4 a0 = *reinterpret_cast<const float4*>(&As[k][ty * 8]);
                float4 a1 = *reinterpret_cast<const float4*>(&As[k][ty * 8 + 4]);
                float4 b0 = *reinterpret_cast<const float4*>(&Bs[k][tx * 8]);
                float4 b1 = *reinterpret_cast<const float4*>(&Bs[k][tx * 8 + 4]);
                float a[8] = {a0.x, a0.y, a0.z, a0.w, a1.x, a1.y, a1.z, a1.w};
                float b[8] = {b0.x, b0.y, b0.z, b0.w, b1.x, b1.y, b1.z, b1.w};
#pragma unroll
                for (int r = 0; r < 8; r++)
#pragma unroll
                    for (int c = 0; c < 8; c++)
                        acc[r][c] = fmaf(a[r], b[c], acc[r][c]);
            }
            __syncthreads();
        }

        // exp-sum + diag capture for this 128x128 tile
#pragma unroll
        for (int r = 0; r < 8; r++) {
            const int row = rowBase + ty * 8 + r;
#pragma unroll
            for (int c = 0; c < 8; c++) {
                float logit = acc[r][c] * INV_TEMP;
                rowsum[r] += __expf(logit - INV_TEMP);
                int col = colBase + tx * 8 + c;
                if (col == row) g_diag[row] = logit;   // written exactly once grid-wide
            }
        }
    }

    // Reduce rowsum across the 16 tx threads sharing a row (half-warp shfl),
    // then one atomicAdd per row per block.
#pragma unroll
    for (int r = 0; r < 8; r++) {
        float v = rowsum[r];
#pragma unroll
        for (int o = 8; o; o >>= 1) v += __shfl_xor_sync(0xffffffffu, v, o);
        if (tx == 0) atomicAdd(&g_S[rowBase + ty * 8 + r], v);
    }
}

// ---------------------------------------------------------------------------
// Kernel 3: result = mean_i( M + log(S_i) - diag_i )
// ---------------------------------------------------------------------------
__global__ void finalize_kernel(float* __restrict__ out) {
    __shared__ float red[8];
    float local = 0.0f;
    for (int i = threadIdx.x; i < NROWS; i += blockDim.x)
        local += INV_TEMP + logf(g_S[i]) - g_diag[i];

    int lane = threadIdx.x & 31;
    int warp = threadIdx.x >> 5;
#pragma unroll
    for (int o = 16; o; o >>= 1) local += __shfl_xor_sync(0xffffffffu, local, o);
    if (lane == 0) red[warp] = local;
    __syncthreads();
    if (threadIdx.x < 32) {
        float v = (threadIdx.x < 8) ? red[threadIdx.x] : 0.0f;
#pragma unroll
        for (int o = 4; o; o >>= 1) v += __shfl_xor_sync(0xffffffffu, v, o);
        if (threadIdx.x == 0) out[0] = v / (float)NROWS;
    }
}

// ---------------------------------------------------------------------------
extern "C" void kernel_launch(void* const* d_in, const int* in_sizes, int n_in,
                              void* d_out, int out_size) {
    const float* q = (const float*)d_in[0];
    const float* k = (const float*)d_in[1];
    (void)in_sizes; (void)n_in; (void)out_size;

    normalize_kernel<<<dim3(NROWS / 8, 2), 256>>>(q, k);
    gemm_lse_kernel<<<dim3(NROWS / BM, NSPLIT), 256>>>();
    finalize_kernel<<<1, 256>>>((float*)d_out);
}

// round 3
// speedup vs baseline: 17.5932x; 17.5932x over previous
#include <cuda_runtime.h>
#include <cuda_bf16.h>
#include <cstdint>
#include <math.h>

#define NROWS 16384
#define DDIM  256
#define INV_TEMP 14.285714285714286f
#define KCA 20.609640474436812f   /* (1/0.07)*log2(e) */

// ---------------------------------------------------------------------------
// Scratch (no allocations allowed)
// ---------------------------------------------------------------------------
__device__ __nv_bfloat16 g_qn[NROWS * DDIM];
__device__ __nv_bfloat16 g_kn[NROWS * DDIM];
__device__ float g_S[NROWS];
__device__ float g_diag[NROWS];

// ---------------------------------------------------------------------------
// PTX helpers (base ISA only: works at target sm_103)
// ---------------------------------------------------------------------------
__device__ __forceinline__ uint32_t smem_u32(const void* p) {
    uint32_t a;
    asm("{ .reg .u64 t; cvta.to.shared.u64 t, %1; cvt.u32.u64 %0, t; }" : "=r"(a) : "l"(p));
    return a;
}
__device__ __forceinline__ void ldsm_x4(uint32_t* r, uint32_t addr) {
    asm volatile("ldmatrix.sync.aligned.m8n8.x4.shared.b16 {%0,%1,%2,%3}, [%4];"
                 : "=r"(r[0]), "=r"(r[1]), "=r"(r[2]), "=r"(r[3]) : "r"(addr));
}
__device__ __forceinline__ void mma_16816(float* d, const uint32_t* a, const uint32_t* b) {
    asm volatile("mma.sync.aligned.m16n8k16.row.col.f32.bf16.bf16.f32 "
                 "{%0,%1,%2,%3}, {%4,%5,%6,%7}, {%8,%9}, {%0,%1,%2,%3};"
                 : "+f"(d[0]), "+f"(d[1]), "+f"(d[2]), "+f"(d[3])
                 : "r"(a[0]), "r"(a[1]), "r"(a[2]), "r"(a[3]), "r"(b[0]), "r"(b[1]));
}
#define CP_ASYNC16(dst, src) \
    asm volatile("cp.async.cg.shared.global [%0], [%1], 16;" :: "r"(dst), "l"(src) : "memory")
#define CP_COMMIT() asm volatile("cp.async.commit_group;" ::: "memory")
#define CP_WAIT1()  asm volatile("cp.async.wait_group 1;" ::: "memory")

// Fast exp2 on the FMA/ALU pipes (avoids the MUFU rt=8 bottleneck).
// Valid for x in [-126, 80]; here x in [-42, 0.3]. abs/rel err ~4e-5.
__device__ __forceinline__ float fast_exp2(float x) {
    float r = x + 12582912.0f;              // round-to-nearest-int via magic
    float n = r - 12582912.0f;
    float f = x - n;                        // f in [-0.5, 0.5]
    int   e = __float_as_int(r) - 0x4B400000;
    float p = fmaf(f, 0.0096181291f, 0.0555041086f);
    p = fmaf(f, p, 0.2402265069f);
    p = fmaf(f, p, 0.6931471806f);
    p = fmaf(f, p, 1.0f);
    return p * __int_as_float((127 + e) << 23);
}

// ---------------------------------------------------------------------------
// Kernel 1: L2 normalize fp32 -> bf16 (one warp per row); zero g_S.
// ---------------------------------------------------------------------------
__global__ void normalize_kernel(const float* __restrict__ q,
                                 const float* __restrict__ k) {
    int warp = threadIdx.x >> 5;
    int lane = threadIdx.x & 31;
    int row  = blockIdx.x * (blockDim.x >> 5) + warp;
    if (row >= NROWS) return;

    const float*   src = (blockIdx.y == 0) ? q : k;
    __nv_bfloat16* dst = (blockIdx.y == 0) ? g_qn : g_kn;

    const float4* s4 = reinterpret_cast<const float4*>(src + (size_t)row * DDIM);
    float4 v0 = s4[2 * lane];
    float4 v1 = s4[2 * lane + 1];

    float ss = v0.x * v0.x + v0.y * v0.y + v0.z * v0.z + v0.w * v0.w
             + v1.x * v1.x + v1.y * v1.y + v1.z * v1.z + v1.w * v1.w;
#pragma unroll
    for (int o = 16; o; o >>= 1) ss += __shfl_xor_sync(0xffffffffu, ss, o);
    float inv = 1.0f / fmaxf(sqrtf(ss), 1e-12f);

    __nv_bfloat162 h[4];
    h[0] = __floats2bfloat162_rn(v0.x * inv, v0.y * inv);
    h[1] = __floats2bfloat162_rn(v0.z * inv, v0.w * inv);
    h[2] = __floats2bfloat162_rn(v1.x * inv, v1.y * inv);
    h[3] = __floats2bfloat162_rn(v1.z * inv, v1.w * inv);
    *reinterpret_cast<uint4*>(dst + (size_t)row * DDIM + lane * 8) =
        *reinterpret_cast<uint4*>(h);

    if (blockIdx.y == 0 && lane == 0) g_S[row] = 0.0f;
}

// ---------------------------------------------------------------------------
// Kernel 2: bf16 mma.sync GEMM (qn @ kn^T) fused with exp-sum epilogue.
// Tile 128x128, BK=32, 3-stage cp.async pipeline, 8 warps (4m x 2n), each
// warp computes 32x64 via m16n8k16. SMEM swizzle: 64B rows, chunk^=(r>>1)&3.
// ---------------------------------------------------------------------------
#define STG_BYTES 16384   /* A 8KB + B 8KB per stage */

__global__ void __launch_bounds__(256, 2) gemm_lse_mma() {
    __shared__ __align__(1024) char smem[3 * STG_BYTES];
    const uint32_t sb = smem_u32(smem);

    const int tid  = threadIdx.x;
    const int lane = tid & 31;
    const int wid  = tid >> 5;
    const int wm   = wid >> 1;      // 0..3 (32-row slice)
    const int wn   = wid & 1;       // 0..1 (64-col slice)
    const int bx   = blockIdx.x;    // col tile
    const int by   = blockIdx.y;    // row tile
    const int rowBase = by * 128;
    const int colBase = bx * 128;

    // --- precompute swizzled ldmatrix offsets (relative to stage base) ---
    uint32_t offA[2][2], offB[4][2];
#pragma unroll
    for (int mi = 0; mi < 2; mi++)
#pragma unroll
        for (int ks = 0; ks < 2; ks++) {
            int r = wm * 32 + mi * 16 + (lane & 15);
            int c = ks * 2 + (lane >> 4);
            offA[mi][ks] = r * 64 + ((c ^ ((r >> 1) & 3)) << 4);
        }
#pragma unroll
    for (int ni = 0; ni < 4; ni++)
#pragma unroll
        for (int ks = 0; ks < 2; ks++) {
            int r = wn * 64 + ni * 16 + (lane & 7) + ((lane >> 4) << 3);
            int c = ks * 2 + ((lane >> 3) & 1);
            offB[ni][ks] = 8192 + r * 64 + ((c ^ ((r >> 1) & 3)) << 4);
        }

    // --- stage loader: 2 A-chunks + 2 B-chunks of 16B per thread ---
    auto load_stage = [&](int kb, int s) {
#pragma unroll
        for (int h = 0; h < 2; h++) {
            int j = tid + h * 256;          // 0..511
            int r = j >> 2, c = j & 3;
            uint32_t dst = sb + s * STG_BYTES + r * 64 + ((c ^ ((r >> 1) & 3)) << 4);
            const __nv_bfloat16* sa = g_qn + (size_t)(rowBase + r) * DDIM + kb * 32 + c * 8;
            CP_ASYNC16(dst, sa);
            const __nv_bfloat16* sbp = g_kn + (size_t)(colBase + r) * DDIM + kb * 32 + c * 8;
            CP_ASYNC16(dst + 8192, sbp);
        }
        CP_COMMIT();
    };

    float acc[2][8][4];
#pragma unroll
    for (int mi = 0; mi < 2; mi++)
#pragma unroll
        for (int ni = 0; ni < 8; ni++)
#pragma unroll
            for (int e = 0; e < 4; e++) acc[mi][ni][e] = 0.0f;

    load_stage(0, 0);
    load_stage(1, 1);

    for (int kb = 0; kb < 8; kb++) {
        CP_WAIT1();
        __syncthreads();
        if (kb + 2 < 8) load_stage(kb + 2, (kb + 2) % 3);

        const uint32_t stg = sb + (kb % 3) * STG_BYTES;
#pragma unroll
        for (int ks = 0; ks < 2; ks++) {
            uint32_t af[2][4], bf[4][4];
            ldsm_x4(af[0], stg + offA[0][ks]);
            ldsm_x4(af[1], stg + offA[1][ks]);
#pragma unroll
            for (int ni = 0; ni < 4; ni++) ldsm_x4(bf[ni], stg + offB[ni][ks]);
#pragma unroll
            for (int mi = 0; mi < 2; mi++)
#pragma unroll
                for (int ni = 0; ni < 4; ni++) {
                    mma_16816(acc[mi][ni * 2 + 0], af[mi], &bf[ni][0]);
                    mma_16816(acc[mi][ni * 2 + 1], af[mi], &bf[ni][2]);
                }
        }
    }

    // --- fused epilogue: exp2 row-sums + diag capture ---
    float rs[2][2] = {{0.0f, 0.0f}, {0.0f, 0.0f}};
    const bool diagblk = (bx == by);
#pragma unroll
    for (int mi = 0; mi < 2; mi++)
#pragma unroll
        for (int ni = 0; ni < 8; ni++)
#pragma unroll
            for (int e = 0; e < 4; e++) {
                float d = acc[mi][ni][e];
                rs[mi][e >> 1] += fast_exp2(fmaf(d, KCA, -KCA));
                if (diagblk) {
                    int grow = rowBase + wm * 32 + mi * 16 + ((e >> 1) << 3) + (lane >> 2);
                    int gcol = colBase + wn * 64 + ni * 8 + ((lane & 3) << 1) + (e & 1);
                    if (grow == gcol) g_diag[grow] = d * INV_TEMP;
                }
            }

#pragma unroll
    for (int mi = 0; mi < 2; mi++)
#pragma unroll
        for (int hf = 0; hf < 2; hf++) {
            float v = rs[mi][hf];
            v += __shfl_xor_sync(0xffffffffu, v, 1);
            v += __shfl_xor_sync(0xffffffffu, v, 2);
            if ((lane & 3) == 0) {
                int grow = rowBase + wm * 32 + mi * 16 + hf * 8 + (lane >> 2);
                atomicAdd(&g_S[grow], v);
            }
        }
}

// ---------------------------------------------------------------------------
// Kernel 3: loss = mean_i( M + log(S_i) - diag_i )
// ---------------------------------------------------------------------------
__global__ void finalize_kernel(float* __restrict__ out) {
    __shared__ float red[8];
    float local = 0.0f;
    for (int i = threadIdx.x; i < NROWS; i += blockDim.x)
        local += INV_TEMP + logf(g_S[i]) - g_diag[i];

    int lane = threadIdx.x & 31;
    int warp = threadIdx.x >> 5;
#pragma unroll
    for (int o = 16; o; o >>= 1) local += __shfl_xor_sync(0xffffffffu, local, o);
    if (lane == 0) red[warp] = local;
    __syncthreads();
    if (threadIdx.x < 32) {
        float v = (threadIdx.x < 8) ? red[threadIdx.x] : 0.0f;
#pragma unroll
        for (int o = 4; o; o >>= 1) v += __shfl_xor_sync(0xffffffffu, v, o);
        if (threadIdx.x == 0) out[0] = v / (float)NROWS;
    }
}

// ---------------------------------------------------------------------------
extern "C" void kernel_launch(void* const* d_in, const int* in_sizes, int n_in,
                              void* d_out, int out_size) {
    const float* q = (const float*)d_in[0];
    const float* k = (const float*)d_in[1];
    (void)in_sizes; (void)n_in; (void)out_size;

    normalize_kernel<<<dim3(NROWS / 8, 2), 256>>>(q, k);
    gemm_lse_mma<<<dim3(NROWS / 128, NROWS / 128), 256>>>();
    finalize_kernel<<<1, 256>>>((float*)d_out);
}